// round 4
// baseline (speedup 1.0000x reference)
#include <cuda_runtime.h>

static constexpr int  B      = 256;
static constexpr int  H      = 512;
static constexpr long N_ELEM = 256L * 3 * 64 * 64;   // 3,145,728
static constexpr long N4     = N_ELEM / 4;           // 786,432 float4
static constexpr int  GRID   = 512;
static constexpr int  TPB    = 512;
static constexpr int  ITERS  = (int)(N4 / ((long)GRID * TPB));  // == 3, exact
static constexpr int  NWARP  = TPB / 32;                         // 16

// Per-block float partials (fully overwritten each launch before the counter
// bump, so no init kernel needed). g_count is zero-init at load and reset by
// the last block every launch.
__device__ float        g_part_mse[GRID];
__device__ float        g_part_pt[B];
__device__ unsigned int g_count;

__device__ __forceinline__ float warp_reduce_f(float v) {
    #pragma unroll
    for (int off = 16; off > 0; off >>= 1)
        v += __shfl_xor_sync(0xFFFFFFFFu, v, off);
    return v;
}
__device__ __forceinline__ double warp_reduce_d(double v) {
    #pragma unroll
    for (int off = 16; off > 0; off >>= 1)
        v += __shfl_xor_sync(0xFFFFFFFFu, v, off);
    return v;
}

__global__ void __launch_bounds__(TPB)
fused_loss_kernel(const float4* __restrict__ y4,
                  const float4* __restrict__ x4,
                  const float*  __restrict__ z,
                  float* __restrict__ out)
{
    const int tid  = threadIdx.x;
    const int lane = tid & 31;
    const int wid  = tid >> 5;
    const bool has_z = (blockIdx.x < B);

    __shared__ float s_mse[NWARP];
    __shared__ float s_s2[NWARP];
    __shared__ float s_s4[NWARP];
    __shared__ bool  s_is_last;

    // ---- front-batch ALL loads (6 LDG.128 + optional 1 LDG.32) ----
    const long base   = (long)blockIdx.x * TPB + tid;
    const long stride = (long)GRID * TPB;

    float4 ya[ITERS], xa[ITERS];
    #pragma unroll
    for (int k = 0; k < ITERS; k++) ya[k] = y4[base + k * stride];
    #pragma unroll
    for (int k = 0; k < ITERS; k++) xa[k] = x4[base + k * stride];

    // z term: blocks 0..255 each own one batch row; TPB==H -> 1 float/thread
    float zv = has_z ? z[(long)blockIdx.x * H + tid] : 0.0f;

    // ---- MSE math ----
    float acc = 0.0f;
    #pragma unroll
    for (int k = 0; k < ITERS; k++) {
        float d0 = ya[k].x - xa[k].x;
        float d1 = ya[k].y - xa[k].y;
        float d2 = ya[k].z - xa[k].z;
        float d3 = ya[k].w - xa[k].w;
        acc += d0 * d0 + d1 * d1 + d2 * d2 + d3 * d3;
    }

    float q  = zv * zv;       // z^2
    float q2 = q * q;         // z^4

    acc = warp_reduce_f(acc);
    q   = warp_reduce_f(q);
    q2  = warp_reduce_f(q2);
    if (lane == 0) { s_mse[wid] = acc; s_s2[wid] = q; s_s4[wid] = q2; }
    __syncthreads();

    // ---- block combine -> private partial slots ----
    if (wid == 0) {
        float m  = (lane < NWARP) ? s_mse[lane] : 0.0f;
        float t2 = (lane < NWARP) ? s_s2[lane]  : 0.0f;
        float t4 = (lane < NWARP) ? s_s4[lane]  : 0.0f;
        m  = warp_reduce_f(m);
        t2 = warp_reduce_f(t2);
        t4 = warp_reduce_f(t4);
        if (lane == 0) {
            g_part_mse[blockIdx.x] = m;
            if (has_z) {
                double d2 = (double)t2;
                g_part_pt[blockIdx.x] = (float)(1.0 - (double)t4 / (d2 * d2));
            }
        }
    }

    // ---- arrival counter; last block finalizes ----
    if (tid == 0) {
        __threadfence();
        unsigned prev = atomicAdd(&g_count, 1u);
        s_is_last = (prev == (unsigned)(GRID - 1));
    }
    __syncthreads();
    if (!s_is_last) return;

    __threadfence();  // acquire: order partial reads after counter observation

    __shared__ double sd_mse[NWARP];
    __shared__ double sd_pt[NWARP];

    double dm = (double)__ldcg(&g_part_mse[tid]);                 // 512 floats, 1 each
    double dp = (tid < B) ? (double)__ldcg(&g_part_pt[tid]) : 0.0;

    dm = warp_reduce_d(dm);
    dp = warp_reduce_d(dp);
    if (lane == 0) { sd_mse[wid] = dm; sd_pt[wid] = dp; }
    __syncthreads();

    if (tid == 0) {
        double sum_sq = 0.0, sum_pt = 0.0;
        #pragma unroll
        for (int w = 0; w < NWARP; w++) { sum_sq += sd_mse[w]; sum_pt += sd_pt[w]; }

        double mse = sum_sq / (double)N_ELEM;
        double pt  = sum_pt / ((double)B * (double)H * (double)H);
        out[0] = (float)(mse + 0.1 * pt);

        g_count = 0u;   // reset for next graph replay
    }
}

extern "C" void kernel_launch(void* const* d_in, const int* in_sizes, int n_in,
                              void* d_out, int out_size)
{
    const float4* y4 = (const float4*)d_in[0];   // yhat_xhat
    const float4* x4 = (const float4*)d_in[1];   // xhat
    const float*  z  = (const float*)d_in[2];    // z_xhat
    float* out = (float*)d_out;

    fused_loss_kernel<<<GRID, TPB>>>(y4, x4, z, out);
}

// round 5
// speedup vs baseline: 1.0842x; 1.0842x over previous
#include <cuda_runtime.h>

static constexpr int  B      = 256;
static constexpr int  H      = 512;
static constexpr long N_ELEM = 256L * 3 * 64 * 64;   // 3,145,728
static constexpr long N4     = N_ELEM / 4;           // 786,432 float4
static constexpr int  GRID   = 2048;
static constexpr int  TPB    = 128;
static constexpr int  ITERS  = (int)(N4 / ((long)GRID * TPB));  // == 3, exact
static constexpr int  NWARP  = TPB / 32;                         // 4

// Per-block float partials; fully overwritten each launch before the counter
// bump. g_count zero-init at load, reset by the last block each launch.
__device__ float        g_part_mse[GRID];   // read back as float4
__device__ float        g_part_pt[B];       // read back as float2
__device__ unsigned int g_count;

__device__ __forceinline__ float warp_reduce_f(float v) {
    #pragma unroll
    for (int off = 16; off > 0; off >>= 1)
        v += __shfl_xor_sync(0xFFFFFFFFu, v, off);
    return v;
}
__device__ __forceinline__ double warp_reduce_d(double v) {
    #pragma unroll
    for (int off = 16; off > 0; off >>= 1)
        v += __shfl_xor_sync(0xFFFFFFFFu, v, off);
    return v;
}

__global__ void __launch_bounds__(TPB)
fused_loss_kernel(const float4* __restrict__ y4,
                  const float4* __restrict__ x4,
                  const float4* __restrict__ z4,
                  float* __restrict__ out)
{
    const int tid  = threadIdx.x;
    const int lane = tid & 31;
    const int wid  = tid >> 5;
    const bool has_z = (blockIdx.x < B);

    __shared__ float s_mse[NWARP];
    __shared__ float s_s2[NWARP];
    __shared__ float s_s4[NWARP];
    __shared__ bool  s_is_last;

    // ---- front-batch ALL loads: 6 LDG.128 (+1 LDG.128 for z blocks) ----
    const long base   = (long)blockIdx.x * TPB + tid;
    const long stride = (long)GRID * TPB;

    float4 ya[ITERS], xa[ITERS];
    #pragma unroll
    for (int k = 0; k < ITERS; k++) ya[k] = y4[base + k * stride];
    #pragma unroll
    for (int k = 0; k < ITERS; k++) xa[k] = x4[base + k * stride];

    // z: blocks 0..255 own one batch row; 128 thr * 4 floats = 512 = H
    float4 zv = make_float4(0.f, 0.f, 0.f, 0.f);
    if (has_z) zv = z4[(long)blockIdx.x * (H / 4) + tid];

    // ---- MSE math ----
    float acc = 0.0f;
    #pragma unroll
    for (int k = 0; k < ITERS; k++) {
        float d0 = ya[k].x - xa[k].x;
        float d1 = ya[k].y - xa[k].y;
        float d2 = ya[k].z - xa[k].z;
        float d3 = ya[k].w - xa[k].w;
        acc += d0 * d0 + d1 * d1 + d2 * d2 + d3 * d3;
    }

    float q0 = zv.x * zv.x, q1 = zv.y * zv.y, q2 = zv.z * zv.z, q3 = zv.w * zv.w;
    float s2 = q0 + q1 + q2 + q3;
    float s4 = q0 * q0 + q1 * q1 + q2 * q2 + q3 * q3;

    acc = warp_reduce_f(acc);
    s2  = warp_reduce_f(s2);
    s4  = warp_reduce_f(s4);
    if (lane == 0) { s_mse[wid] = acc; s_s2[wid] = s2; s_s4[wid] = s4; }
    __syncthreads();

    // ---- block combine -> private partial slots ----
    if (tid == 0) {
        float m  = s_mse[0] + s_mse[1] + s_mse[2] + s_mse[3];
        g_part_mse[blockIdx.x] = m;
        if (has_z) {
            double d2 = (double)(s_s2[0] + s_s2[1] + s_s2[2] + s_s2[3]);
            double d4 = (double)(s_s4[0] + s_s4[1] + s_s4[2] + s_s4[3]);
            g_part_pt[blockIdx.x] = (float)(1.0 - d4 / (d2 * d2));
        }
        __threadfence();
        unsigned prev = atomicAdd(&g_count, 1u);
        s_is_last = (prev == (unsigned)(GRID - 1));
    }
    __syncthreads();
    if (!s_is_last) return;

    // ---- last block: reduce 2048 mse-partials (float4 x 512) + 256 pt (float2 x 128) ----
    __threadfence();  // acquire ordering after observing all arrivals

    __shared__ double sd_mse[NWARP];
    __shared__ double sd_pt[NWARP];

    const float4* pm4 = reinterpret_cast<const float4*>(g_part_mse);
    double dm = 0.0;
    #pragma unroll
    for (int k = 0; k < (GRID / 4) / TPB; k++) {           // 4 float4 per thread
        float4 v = __ldcg(&pm4[tid + k * TPB]);
        dm += (double)((v.x + v.y) + (v.z + v.w));
    }

    double dp = 0.0;
    if (tid < B / 2) {
        float2 v = __ldcg(&reinterpret_cast<const float2*>(g_part_pt)[tid]);
        dp = (double)v.x + (double)v.y;
    }

    dm = warp_reduce_d(dm);
    dp = warp_reduce_d(dp);
    if (lane == 0) { sd_mse[wid] = dm; sd_pt[wid] = dp; }
    __syncthreads();

    if (tid == 0) {
        double sum_sq = sd_mse[0] + sd_mse[1] + sd_mse[2] + sd_mse[3];
        double sum_pt = sd_pt[0] + sd_pt[1] + sd_pt[2] + sd_pt[3];

        double mse = sum_sq / (double)N_ELEM;
        double pt  = sum_pt / ((double)B * (double)H * (double)H);
        out[0] = (float)(mse + 0.1 * pt);

        g_count = 0u;   // reset for next graph replay
    }
}

extern "C" void kernel_launch(void* const* d_in, const int* in_sizes, int n_in,
                              void* d_out, int out_size)
{
    const float4* y4 = (const float4*)d_in[0];   // yhat_xhat
    const float4* x4 = (const float4*)d_in[1];   // xhat
    const float4* z4 = (const float4*)d_in[2];   // z_xhat
    float* out = (float*)d_out;

    fused_loss_kernel<<<GRID, TPB>>>(y4, x4, z4, out);
}

// round 6
// speedup vs baseline: 1.1599x; 1.0698x over previous
#include <cuda_runtime.h>

static constexpr int  B      = 256;
static constexpr int  H      = 512;
static constexpr long N_ELEM = 256L * 3 * 64 * 64;   // 3,145,728
static constexpr long N4     = N_ELEM / 4;           // 786,432 float4
static constexpr int  GRID   = 1024;                 // measured-optimal shape
static constexpr int  TPB    = 256;
static constexpr int  ITERS  = (int)(N4 / ((long)GRID * TPB));  // == 3, exact
static constexpr int  NWARP  = TPB / 32;                         // 8

// Per-block float partials; fully overwritten each launch before the counter
// bump. g_count zero-init at load, reset by the last block each launch.
__device__ float        g_part_mse[GRID];   // finalize reads as float4
__device__ float        g_part_pt[B];       // finalize reads as float2
__device__ unsigned int g_count;

__device__ __forceinline__ float warp_reduce_f(float v) {
    #pragma unroll
    for (int off = 16; off > 0; off >>= 1)
        v += __shfl_xor_sync(0xFFFFFFFFu, v, off);
    return v;
}
__device__ __forceinline__ double warp_reduce_d(double v) {
    #pragma unroll
    for (int off = 16; off > 0; off >>= 1)
        v += __shfl_xor_sync(0xFFFFFFFFu, v, off);
    return v;
}

__global__ void __launch_bounds__(TPB)
fused_loss_kernel(const float4* __restrict__ y4,
                  const float4* __restrict__ x4,
                  const float2* __restrict__ z2,
                  float* __restrict__ out)
{
    const int tid  = threadIdx.x;
    const int lane = tid & 31;
    const int wid  = tid >> 5;
    const bool has_z = (blockIdx.x < B);

    __shared__ float s_mse[NWARP];
    __shared__ float s_s2[NWARP];
    __shared__ float s_s4[NWARP];
    __shared__ bool  s_is_last;

    // ---- front-batch ALL loads: 6x LDG.128 (+1 LDG.64 for z blocks) ----
    const long base   = (long)blockIdx.x * TPB + tid;
    const long stride = (long)GRID * TPB;

    float2 zv = make_float2(0.f, 0.f);
    if (has_z) zv = z2[(long)blockIdx.x * (H / 2) + tid];   // 256 thr * 2 = 512 = H

    float4 ya[ITERS], xa[ITERS];
    #pragma unroll
    for (int k = 0; k < ITERS; k++) ya[k] = y4[base + k * stride];
    #pragma unroll
    for (int k = 0; k < ITERS; k++) xa[k] = x4[base + k * stride];

    // ---- MSE math ----
    float acc = 0.0f;
    #pragma unroll
    for (int k = 0; k < ITERS; k++) {
        float d0 = ya[k].x - xa[k].x;
        float d1 = ya[k].y - xa[k].y;
        float d2 = ya[k].z - xa[k].z;
        float d3 = ya[k].w - xa[k].w;
        acc += d0 * d0 + d1 * d1 + d2 * d2 + d3 * d3;
    }

    // ---- z math ----
    float q0 = zv.x * zv.x, q1 = zv.y * zv.y;
    float s2 = q0 + q1;
    float s4 = q0 * q0 + q1 * q1;

    acc = warp_reduce_f(acc);
    s2  = warp_reduce_f(s2);
    s4  = warp_reduce_f(s4);
    if (lane == 0) { s_mse[wid] = acc; s_s2[wid] = s2; s_s4[wid] = s4; }
    __syncthreads();

    // ---- block combine (thread 0) -> private partial slots, then counter ----
    if (tid == 0) {
        float m = 0.f, t2 = 0.f, t4 = 0.f;
        #pragma unroll
        for (int w = 0; w < NWARP; w++) { m += s_mse[w]; t2 += s_s2[w]; t4 += s_s4[w]; }
        g_part_mse[blockIdx.x] = m;
        if (has_z) {
            double d2 = (double)t2;
            g_part_pt[blockIdx.x] = (float)(1.0 - (double)t4 / (d2 * d2));
        }
        __threadfence();
        unsigned prev = atomicAdd(&g_count, 1u);
        s_is_last = (prev == (unsigned)(GRID - 1));
    }
    __syncthreads();
    if (!s_is_last) return;

    // ---- last block: reduce 1024 mse partials (float4 x 256) + 256 pt (float2 x 128) ----
    __threadfence();  // acquire: order partial reads after seeing all arrivals

    __shared__ double sd_mse[NWARP];
    __shared__ double sd_pt[NWARP];

    float4 pm = __ldcg(&reinterpret_cast<const float4*>(g_part_mse)[tid]);  // 1 per thread
    double dm = (double)((pm.x + pm.y) + (pm.z + pm.w));

    double dp = 0.0;
    if (tid < B / 2) {
        float2 v = __ldcg(&reinterpret_cast<const float2*>(g_part_pt)[tid]);
        dp = (double)v.x + (double)v.y;
    }

    dm = warp_reduce_d(dm);
    dp = warp_reduce_d(dp);
    if (lane == 0) { sd_mse[wid] = dm; sd_pt[wid] = dp; }
    __syncthreads();

    if (tid == 0) {
        double sum_sq = 0.0, sum_pt = 0.0;
        #pragma unroll
        for (int w = 0; w < NWARP; w++) { sum_sq += sd_mse[w]; sum_pt += sd_pt[w]; }

        double mse = sum_sq / (double)N_ELEM;
        double pt  = sum_pt / ((double)B * (double)H * (double)H);
        out[0] = (float)(mse + 0.1 * pt);

        g_count = 0u;   // reset for next graph replay
    }
}

extern "C" void kernel_launch(void* const* d_in, const int* in_sizes, int n_in,
                              void* d_out, int out_size)
{
    const float4* y4 = (const float4*)d_in[0];   // yhat_xhat
    const float4* x4 = (const float4*)d_in[1];   // xhat
    const float2* z2 = (const float2*)d_in[2];   // z_xhat
    float* out = (float*)d_out;

    fused_loss_kernel<<<GRID, TPB>>>(y4, x4, z2, out);
}

// round 7
// speedup vs baseline: 1.1910x; 1.0269x over previous
#include <cuda_runtime.h>

static constexpr int  B      = 256;
static constexpr int  H      = 512;
static constexpr long N_ELEM = 256L * 3 * 64 * 64;   // 3,145,728
static constexpr long N4     = N_ELEM / 4;           // 786,432 float4
static constexpr int  GRID   = 1024;                 // measured-optimal shape
static constexpr int  TPB    = 256;
static constexpr int  ITERS  = (int)(N4 / ((long)GRID * TPB));  // == 3, exact
static constexpr int  NWARP  = TPB / 32;                         // 8

// Global accumulators: zero at module load; last block resets them every
// launch, so each graph replay starts from zero. All adds are no-return
// float REDs (overlapped with the stream) -> tiny finalize tail.
__device__ float        g_acc_mse;
__device__ float        g_acc_pt;
__device__ unsigned int g_count;

__device__ __forceinline__ float warp_reduce_f(float v) {
    #pragma unroll
    for (int off = 16; off > 0; off >>= 1)
        v += __shfl_xor_sync(0xFFFFFFFFu, v, off);
    return v;
}

__global__ void __launch_bounds__(TPB)
fused_loss_kernel(const float4* __restrict__ y4,
                  const float4* __restrict__ x4,
                  const float2* __restrict__ z2,
                  float* __restrict__ out)
{
    const int tid  = threadIdx.x;
    const int lane = tid & 31;
    const int wid  = tid >> 5;
    const bool has_z = (blockIdx.x < B);

    __shared__ float s_mse[NWARP];
    __shared__ float s_s2[NWARP];
    __shared__ float s_s4[NWARP];
    __shared__ bool  s_is_last;

    // ---- front-batch ALL loads: 6x LDG.128 (+1 LDG.64 for z blocks) ----
    const long base   = (long)blockIdx.x * TPB + tid;
    const long stride = (long)GRID * TPB;

    float2 zv = make_float2(0.f, 0.f);
    if (has_z) zv = z2[(long)blockIdx.x * (H / 2) + tid];   // 256 thr * 2 = 512 = H

    float4 ya[ITERS], xa[ITERS];
    #pragma unroll
    for (int k = 0; k < ITERS; k++) ya[k] = y4[base + k * stride];
    #pragma unroll
    for (int k = 0; k < ITERS; k++) xa[k] = x4[base + k * stride];

    // ---- MSE math ----
    float acc = 0.0f;
    #pragma unroll
    for (int k = 0; k < ITERS; k++) {
        float d0 = ya[k].x - xa[k].x;
        float d1 = ya[k].y - xa[k].y;
        float d2 = ya[k].z - xa[k].z;
        float d3 = ya[k].w - xa[k].w;
        acc += d0 * d0 + d1 * d1 + d2 * d2 + d3 * d3;
    }

    // ---- z math ----
    float q0 = zv.x * zv.x, q1 = zv.y * zv.y;
    float s2 = q0 + q1;
    float s4 = q0 * q0 + q1 * q1;

    acc = warp_reduce_f(acc);
    s2  = warp_reduce_f(s2);
    s4  = warp_reduce_f(s4);
    if (lane == 0) { s_mse[wid] = acc; s_s2[wid] = s2; s_s4[wid] = s4; }
    __syncthreads();

    // ---- block combine (thread 0) -> no-return RED atomics, then counter ----
    if (tid == 0) {
        float m = 0.f, t2 = 0.f, t4 = 0.f;
        #pragma unroll
        for (int w = 0; w < NWARP; w++) { m += s_mse[w]; t2 += s_s2[w]; t4 += s_s4[w]; }

        atomicAdd(&g_acc_mse, m);                        // result unused -> REDG
        if (has_z) {
            double d2 = (double)t2;
            atomicAdd(&g_acc_pt, (float)(1.0 - (double)t4 / (d2 * d2)));
        }

        __threadfence();
        unsigned prev = atomicAdd(&g_count, 1u);
        s_is_last = (prev == (unsigned)(GRID - 1));
    }
    __syncthreads();
    if (!s_is_last) return;

    // ---- last block: trivial finalize (2 loads, 3 flops, 1 store, reset) ----
    if (tid == 0) {
        // atomic reads force L2-coherent values after all arrivals observed
        float sum_sq = atomicAdd(&g_acc_mse, 0.0f);
        float sum_pt = atomicAdd(&g_acc_pt, 0.0f);

        double mse = (double)sum_sq / (double)N_ELEM;
        double pt  = (double)sum_pt / ((double)B * (double)H * (double)H);
        out[0] = (float)(mse + 0.1 * pt);

        // reset for next graph replay
        g_acc_mse = 0.0f;
        g_acc_pt  = 0.0f;
        __threadfence();
        g_count = 0u;
    }
}

extern "C" void kernel_launch(void* const* d_in, const int* in_sizes, int n_in,
                              void* d_out, int out_size)
{
    const float4* y4 = (const float4*)d_in[0];   // yhat_xhat
    const float4* x4 = (const float4*)d_in[1];   // xhat
    const float2* z2 = (const float2*)d_in[2];   // z_xhat
    float* out = (float*)d_out;

    fused_loss_kernel<<<GRID, TPB>>>(y4, x4, z2, out);
}

// round 8
// speedup vs baseline: 1.4723x; 1.2362x over previous
#include <cuda_runtime.h>

static constexpr int  B      = 256;
static constexpr int  H      = 512;
static constexpr long N_ELEM = 256L * 3 * 64 * 64;   // 3,145,728
static constexpr long N4     = N_ELEM / 4;           // 786,432 float4
static constexpr int  GRID   = 512;
static constexpr int  TPB    = 256;
static constexpr int  ITERS  = (int)(N4 / ((long)GRID * TPB));  // == 6, exact
static constexpr int  NWARP  = TPB / 32;                         // 8

// Global accumulators: zero at module load; last block resets them every
// launch so each graph replay starts from zero.
__device__ float        g_acc_mse;
__device__ float        g_acc_pt;
__device__ unsigned int g_count;

__device__ __forceinline__ float warp_reduce_f(float v) {
    #pragma unroll
    for (int off = 16; off > 0; off >>= 1)
        v += __shfl_xor_sync(0xFFFFFFFFu, v, off);
    return v;
}

__global__ void __launch_bounds__(TPB)
fused_loss_kernel(const float4* __restrict__ y4,
                  const float4* __restrict__ x4,
                  const float2* __restrict__ z2,
                  float* __restrict__ out)
{
    const int tid  = threadIdx.x;
    const int lane = tid & 31;
    const int wid  = tid >> 5;
    const bool has_z = (blockIdx.x < B);

    __shared__ float s_mse[NWARP];
    __shared__ float s_s2[NWARP];
    __shared__ float s_s4[NWARP];
    __shared__ bool  s_is_last;

    const long base   = (long)blockIdx.x * TPB + tid;
    const long stride = (long)GRID * TPB;

    // ---- front-batch loads: 12x LDG.128 (+1 LDG.64 for z blocks) ----
    float2 zv = make_float2(0.f, 0.f);
    if (has_z) zv = z2[(long)blockIdx.x * (H / 2) + tid];   // 256 thr * 2 = 512 = H

    float4 ya[ITERS], xa[ITERS];
    #pragma unroll
    for (int k = 0; k < ITERS; k++) ya[k] = y4[base + k * stride];
    #pragma unroll
    for (int k = 0; k < ITERS; k++) xa[k] = x4[base + k * stride];

    // ---- MSE math ----
    float acc = 0.0f;
    #pragma unroll
    for (int k = 0; k < ITERS; k++) {
        float d0 = ya[k].x - xa[k].x;
        float d1 = ya[k].y - xa[k].y;
        float d2 = ya[k].z - xa[k].z;
        float d3 = ya[k].w - xa[k].w;
        acc += d0 * d0 + d1 * d1 + d2 * d2 + d3 * d3;
    }

    // ---- z math ----
    float q0 = zv.x * zv.x, q1 = zv.y * zv.y;
    float s2 = q0 + q1;
    float s4 = q0 * q0 + q1 * q1;

    acc = warp_reduce_f(acc);
    s2  = warp_reduce_f(s2);
    s4  = warp_reduce_f(s4);
    if (lane == 0) { s_mse[wid] = acc; s_s2[wid] = s2; s_s4[wid] = s4; }
    __syncthreads();

    // ---- block combine (thread 0) -> no-return REDs, release-counter ----
    if (tid == 0) {
        float m = 0.f, t2 = 0.f, t4 = 0.f;
        #pragma unroll
        for (int w = 0; w < NWARP; w++) { m += s_mse[w]; t2 += s_s2[w]; t4 += s_s4[w]; }

        atomicAdd(&g_acc_mse, m);                        // no-return -> REDG
        if (has_z) {
            double d2 = (double)t2;
            atomicAdd(&g_acc_pt, (float)(1.0 - (double)t4 / (d2 * d2)));
        }

        // release-atomic on the counter orders the REDs above without a
        // standalone gpu-scope fence (avoids per-CTA CCTL.IVALL/MEMBAR).
        unsigned prev;
        asm volatile("atom.add.release.gpu.global.u32 %0, [%1], %2;"
                     : "=r"(prev) : "l"(&g_count), "r"(1u) : "memory");
        s_is_last = (prev == (unsigned)(GRID - 1));
    }
    __syncthreads();
    if (!s_is_last) return;

    // ---- last block: trivial finalize ----
    if (tid == 0) {
        // atomic RMW reads are serialized at the LTS with all prior REDs ->
        // they observe the complete sums (release on counter + same-address
        // atomic ordering).
        float sum_sq = atomicAdd(&g_acc_mse, 0.0f);
        float sum_pt = atomicAdd(&g_acc_pt, 0.0f);

        double mse = (double)sum_sq / (double)N_ELEM;
        double pt  = (double)sum_pt / ((double)B * (double)H * (double)H);
        out[0] = (float)(mse + 0.1 * pt);

        // reset for next graph replay
        g_acc_mse = 0.0f;
        g_acc_pt  = 0.0f;
        asm volatile("st.release.gpu.global.u32 [%0], %1;"
                     :: "l"(&g_count), "r"(0u) : "memory");
    }
}

extern "C" void kernel_launch(void* const* d_in, const int* in_sizes, int n_in,
                              void* d_out, int out_size)
{
    const float4* y4 = (const float4*)d_in[0];   // yhat_xhat
    const float4* x4 = (const float4*)d_in[1];   // xhat
    const float2* z2 = (const float2*)d_in[2];   // z_xhat
    float* out = (float*)d_out;

    fused_loss_kernel<<<GRID, TPB>>>(y4, x4, z2, out);
}